// round 9
// baseline (speedup 1.0000x reference)
#include <cuda_runtime.h>
#include <cstdint>

#define Bk 128
#define Sk 128
#define Ek 256
#define Dk 512
#define Kk 16
#define Lk 1906
#define Rk 2033
#define Tk 127
#define TINYF 1.17549435e-38f

// smem layout (float offsets)
#define OFF_STA   0        // buffer A: 32x260
#define OFF_STB   8320     // buffer B: 32x260
#define OFF_WA    16640    // W_el tile: 256e x 8dp float2
#define OFF_WBI   20736    // 8dp x 514 float2
#define OFF_WBH   28960
#define OFF_SE    37184    // 16x256 neighbor emb
#define OFF_WMK   41280    // 768
#define OFF_WTM   42048    // 512
#define OFF_WTE   42560    // 256
#define OFF_BTE   42816    // 256
#define OFF_BEL   43072    // 512
#define OFF_BIH   43584    // 512
#define OFF_BHH   44096    // 512
#define OFF_BT    44608    // b_time, b_mk, last_t_my
#define OFF_SLT   44612    // 32
#define OFF_SLM   44644    // 32
#define OFF_CS    44676    // red8, redv8, ri8, neigh16, score16
#define OFF_SP    44740    // prob[1906]
#define OFF_SC    46646    // cand[1906] (int)
#define OFF_SN    48552    // nrec[2033]
#define SM_FLOATS 50592
#define SM_BYTES  (SM_FLOATS * 4)

__device__ float g_h[2][Bk][Dk];
__device__ float g_x[Bk][Dk];
__device__ float g_last_t[Bk];
__device__ int   g_last_m[Bk];
__device__ unsigned g_cnt[4][128];    // arrival counters, 512B apart
__device__ unsigned g_flag[4][128];   // broadcast flags (clean lines), 512B apart

// JAX threefry2x32 (exact)
__device__ __forceinline__ void tf2x32(uint32_t k0, uint32_t k1,
                                       uint32_t x0, uint32_t x1,
                                       uint32_t& o0, uint32_t& o1) {
  uint32_t ks2 = k0 ^ k1 ^ 0x1BD11BDAu;
  x0 += k0; x1 += k1;
#define RR(d) { x0 += x1; x1 = (x1 << d) | (x1 >> (32 - d)); x1 ^= x0; }
  RR(13) RR(15) RR(26) RR(6)  x0 += k1;  x1 += ks2 + 1u;
  RR(17) RR(29) RR(16) RR(24) x0 += ks2; x1 += k0 + 2u;
  RR(13) RR(15) RR(26) RR(6)  x0 += k0;  x1 += k1 + 3u;
  RR(17) RR(29) RR(16) RR(24) x0 += k1;  x1 += ks2 + 4u;
  RR(13) RR(15) RR(26) RR(6)  x0 += ks2; x1 += k0 + 5u;
#undef RR
  o0 = x0; o1 = x1;
}

__device__ __forceinline__ unsigned long long dup2(float v) {
  unsigned long long r;
  asm("mov.b64 %0, {%1, %1};" : "=l"(r) : "f"(v));
  return r;
}
__device__ __forceinline__ void ffma2(unsigned long long& acc,
                                      unsigned long long a,
                                      unsigned long long b) {
  asm("fma.rn.f32x2 %0, %1, %2, %3;" : "=l"(acc) : "l"(a), "l"(b), "l"(acc));
}
__device__ __forceinline__ void cpa16(uint32_t s, const void* g) {
  asm volatile("cp.async.cg.shared.global [%0], [%1], 16;"
               :: "r"(s), "l"(g) : "memory");
}
__device__ __forceinline__ void cpa_commit() {
  asm volatile("cp.async.commit_group;" ::: "memory");
}
template <int N>
__device__ __forceinline__ void cpa_wait_group() {
  asm volatile("cp.async.wait_group %0;" :: "n"(N) : "memory");
}

__global__ void reset_kernel() {
  int tid = threadIdx.x;
  if (tid < 512) ((unsigned*)g_cnt)[tid] = 0u;
  else ((unsigned*)g_flag)[tid - 512] = 0u;
}

// sense-flag group barrier: release-atomic arrive; LAST arriver broadcasts
// epoch on a clean flag line; others poll the flag (no atomic contention).
__device__ __forceinline__ void gbar(int bc, unsigned& epoch) {
  __syncthreads();
  if (threadIdx.x == 0) {
    epoch += 1u;
    unsigned old;
    asm volatile("atom.add.release.gpu.global.u32 %0, [%1], %2;"
                 : "=r"(old) : "l"(&g_cnt[bc][0]), "r"(1u) : "memory");
    if (old == epoch * 32u - 1u) {
      asm volatile("st.release.gpu.global.u32 [%0], %1;"
                   :: "l"(&g_flag[bc][0]), "r"(epoch) : "memory");
    } else {
      while (*((volatile unsigned*)&g_flag[bc][0]) < epoch) { }
    }
  }
  __syncthreads();
}

__global__ void __launch_bounds__(256, 1)
rnn_persistent(const int* __restrict__ marker,
               const float* __restrict__ timed,
               const float* __restrict__ maskd,
               const float* __restrict__ emb,
               const int* __restrict__ nlist,
               const float* __restrict__ nprob,
               const float* __restrict__ W_te,
               const float* __restrict__ b_te,
               const float* __restrict__ W_el,
               const float* __restrict__ b_el,
               const float* __restrict__ W_ih,
               const float* __restrict__ b_ih,
               const float* __restrict__ W_hh,
               const float* __restrict__ b_hh,
               const float* __restrict__ W_time,
               const float* __restrict__ b_time,
               const float* __restrict__ W_mk,
               const float* __restrict__ b_mk,
               float* __restrict__ out) {
  extern __shared__ __align__(16) float SM[];
  const int BID = blockIdx.x;
  if (BID >= 128) return;
  const int tid = threadIdx.x;
  const int bc = BID >> 5;           // group (32 batch rows)
  const int dc = BID & 31;           // d tile (16 cols)
  const int myb = BID;               // phase-C row
  unsigned epoch = 0;

  float* sP = SM + OFF_SP;
  int*   sC = (int*)(SM + OFF_SC);
  float* sN = SM + OFF_SN;

  // ---------------- one-time init ----------------
  for (int i = tid; i < Ek * 8; i += 256) {
    int e = i >> 3, dp8 = i & 7;
    ((float2*)(SM + OFF_WA))[e * 8 + dp8] =
        *(const float2*)&W_el[e * Dk + dc * 16 + dp8 * 2];
  }
  for (int i = tid; i < Dk * 8; i += 256) {
    int e = i >> 3, dp8 = i & 7;
    ((float2*)(SM + OFF_WBI))[dp8 * 514 + e] =
        *(const float2*)&W_ih[e * Dk + dc * 16 + dp8 * 2];
    ((float2*)(SM + OFF_WBH))[dp8 * 514 + e] =
        *(const float2*)&W_hh[e * Dk + dc * 16 + dp8 * 2];
  }
  for (int i = tid; i < Ek + Dk; i += 256) SM[OFF_WMK + i] = W_mk[i];
  for (int i = tid; i < Dk; i += 256) {
    SM[OFF_WTM + i] = W_time[i];
    SM[OFF_BEL + i] = b_el[i];
    SM[OFF_BIH + i] = b_ih[i];
    SM[OFF_BHH + i] = b_hh[i];
  }
  if (tid < Ek) { SM[OFF_WTE + tid] = W_te[tid]; SM[OFF_BTE + tid] = b_te[tid]; }
  if (tid == 0) {
    SM[OFF_BT] = b_time[0]; SM[OFF_BT + 1] = b_mk[0];
    SM[OFF_BT + 2] = timed[myb * Sk];        // last_t (own row)
  }
  for (int l = tid; l < Lk; l += 256) {
    sP[l] = (l == 0) ? 1.0f : 0.0f;
    sC[l] = (l == 0) ? marker[myb * Sk] : 0;
  }
  for (int r = tid; r < Rk; r += 256) sN[r] = 1.0f;
  for (int d = tid; d < Dk; d += 256) __stcg(&g_h[0][myb][d], 0.0f);
  int chosen = 0;
  if (tid == 0) {
    __stcg(&g_last_t[myb], timed[myb * Sk]);
    __stcg(&g_last_m[myb], marker[myb * Sk]);
    out[0 * 16384 + myb * Sk] = (float)marker[myb * Sk];
    out[1 * 16384 + myb * Sk] = timed[myb * Sk];
    out[2 * 16384 + myb * Sk] = maskd[myb * Sk];
    out[3 * 16384 + myb * Sk] = 1.0f;
    out[4 * 16384 + myb * Sk] = 1.0f;
  }
  gbar(bc, epoch);

  const int dp = tid & 7;
  const int blw = tid >> 3;          // 0..31
  const int d0 = dc * 16 + dp * 2;
  const int bg = bc * 32 + blw;
  int*   s_neigh = (int*)(SM + OFF_CS + 24);
  float* s_score = SM + OFF_CS + 40;
  const uint32_t stA = (uint32_t)__cvta_generic_to_shared(SM + OFF_STA);
  const uint32_t stB = (uint32_t)__cvta_generic_to_shared(SM + OFF_STB);
  const uint32_t se_base = (uint32_t)__cvta_generic_to_shared(SM + OFF_SE);

  // stage one 32x256 chunk (Dk-strided source) into a smem buffer
#define STAGE(gptr, ebase, dst)                                           \
  {                                                                       \
    _Pragma("unroll")                                                     \
    for (int j = 0; j < 8; j++) {                                         \
      int id = tid + j * 256;                                             \
      int rr = id >> 6, seg = id & 63;                                    \
      cpa16((dst) + (uint32_t)(rr * 260 + seg * 4) * 4,                   \
            (gptr) + (size_t)(bc * 32 + rr) * Dk + (ebase) + seg * 4);    \
    }                                                                     \
    cpa_commit();                                                         \
  }
#define CHUNK(accv, wbase, half, buf)                                     \
  {                                                                       \
    const float4* pxc = (const float4*)(SM + (buf) + blw * 260);          \
    const ulonglong2* pw =                                                \
        (const ulonglong2*)(SM + (wbase)) + dp * 257 + (half) * 128;      \
    _Pragma("unroll 8")                                                   \
    for (int e4 = 0; e4 < 64; e4++) {                                     \
      float4 q = pxc[e4];                                                 \
      ulonglong2 wA = pw[2 * e4], wB = pw[2 * e4 + 1];                    \
      ffma2(accv, dup2(q.x), wA.x);                                       \
      ffma2(accv, dup2(q.y), wA.y);                                       \
      ffma2(accv, dup2(q.z), wB.x);                                       \
      ffma2(accv, dup2(q.w), wB.y);                                       \
    }                                                                     \
  }

  for (int t = 0; t < Tk; t++) {
    const float* hin = &g_h[t & 1][0][0];
    // ============ Phase A: x = leaky(vec @ W_el + b_el) ============
    {
      if (tid < 32) {
        SM[OFF_SLT + tid] = __ldcg(&g_last_t[bc * 32 + tid]);
        ((int*)(SM + OFF_SLM))[tid] = __ldcg(&g_last_m[bc * 32 + tid]);
      }
      __syncthreads();
      // stage 32 emb rows into bufA (group 1)
#pragma unroll
      for (int j = 0; j < 8; j++) {
        int id = tid + j * 256;
        int bl = id >> 6, seg = id & 63;
        cpa16(stA + (uint32_t)(bl * 260 + seg * 4) * 4,
              emb + (size_t)((int*)(SM + OFF_SLM))[bl] * Ek + seg * 4);
      }
      cpa_commit();
      // prefetch h chunk0 into bufB for phase B (group 2; h(t) is stable)
      STAGE(hin, 0, stB)
      cpa_wait_group<1>();   // emb done (h0 may still be in flight)
      __syncthreads();
      {
        float wte = SM[OFF_WTE + tid], bte = SM[OFF_BTE + tid];
        float* sV = SM + OFF_STA;
#pragma unroll 4
        for (int bl = 0; bl < 32; bl++) {
          float te = __fadd_rn(__fmul_rn(SM[OFF_SLT + bl], wte), bte);
          sV[bl * 260 + tid] = __fadd_rn(sV[bl * 260 + tid], __fmul_rn(0.1f, te));
        }
      }
      __syncthreads();
      const float* pv = SM + OFF_STA + blw * 260;
      const unsigned long long* wa = (const unsigned long long*)(SM + OFF_WA);
      unsigned long long acc2 = 0ull;
#pragma unroll 8
      for (int e = 0; e < Ek; e++) {
        ffma2(acc2, dup2(pv[e]), wa[e * 8 + dp]);
      }
      float a0, a1;
      asm("mov.b64 {%0, %1}, %2;" : "=f"(a0), "=f"(a1) : "l"(acc2));
      a0 = __fadd_rn(a0, SM[OFF_BEL + d0]);
      a1 = __fadd_rn(a1, SM[OFF_BEL + d0 + 1]);
      float2 r;
      r.x = (a0 >= 0.0f) ? a0 : __fmul_rn(0.01f, a0);
      r.y = (a1 >= 0.0f) ? a1 : __fmul_rn(0.01f, a1);
      __stcg((float2*)&g_x[bg][d0], r);

      // prefetch C's neighbor rows (group 3; overlaps phase B)
      int lm_my = ((int*)(SM + OFF_SLM))[dc];
      if (tid < Kk) {
        s_neigh[tid] = nlist[lm_my * Kk + tid];
        sN[1 + t * Kk + tid] = nprob[lm_my * Kk + tid];
      }
      __syncthreads();
#pragma unroll
      for (int j = 0; j < 4; j++) {
        int id = tid + j * 256;
        int k = id >> 6, seg = id & 63;
        cpa16(se_base + (uint32_t)(k * 256 + seg * 4) * 4,
              emb + (size_t)s_neigh[k] * Ek + seg * 4);
      }
      cpa_commit();
    }
    gbar(bc, epoch);

    // ==== Phase B: h' = tanh(x@Wih + b + h@Whh + b), fully hidden staging ====
    {
      unsigned long long axx = 0ull, ahh = 0ull;
      STAGE(&g_x[0][0], 0, stA)        // x0 (group 4)
      cpa_wait_group<2>();             // h0 (group 2) done; SE/x0 may pend
      CHUNK(ahh, OFF_WBH, 0, OFF_STB)  // h chunk 0
      __syncthreads();
      STAGE(hin, 256, stB)             // h1 (group 5)
      cpa_wait_group<1>();             // SE + x0 done
      CHUNK(axx, OFF_WBI, 0, OFF_STA)  // x chunk 0
      __syncthreads();
      STAGE(&g_x[0][0], 256, stA)      // x1 (group 6)
      cpa_wait_group<1>();             // h1 done
      CHUNK(ahh, OFF_WBH, 1, OFF_STB)  // h chunk 1
      __syncthreads();
      cpa_wait_group<0>();             // x1 done
      CHUNK(axx, OFF_WBI, 1, OFF_STA)  // x chunk 1

      float ax0, ax1, ah0, ah1;
      asm("mov.b64 {%0, %1}, %2;" : "=f"(ax0), "=f"(ax1) : "l"(axx));
      asm("mov.b64 {%0, %1}, %2;" : "=f"(ah0), "=f"(ah1) : "l"(ahh));
      float2 r;
      r.x = tanhf(__fadd_rn(__fadd_rn(__fadd_rn(ax0, SM[OFF_BIH + d0]), ah0),
                            SM[OFF_BHH + d0]));
      r.y = tanhf(__fadd_rn(__fadd_rn(__fadd_rn(ax1, SM[OFF_BIH + d0 + 1]), ah1),
                            SM[OFF_BHH + d0 + 1]));
      __stcg((float2*)&g_h[(t + 1) & 1][bg][d0], r);
    }
    gbar(bc, epoch);

    // ============ Phase C: sampling step for row myb ============
    {
      float* hb   = SM + OFF_STA;           // [512]
      float* red  = SM + OFF_CS;            // [8]
      float* redv = SM + OFF_CS + 8;        // [8]
      int*   ri   = (int*)(SM + OFF_CS + 16);
      float* sE   = SM + OFF_SE;
      int warp = tid >> 5, lane = tid & 31;

      hb[tid]       = __ldcg(&g_h[(t + 1) & 1][myb][tid]);
      hb[tid + 256] = __ldcg(&g_h[(t + 1) & 1][myb][tid + 256]);
      __syncthreads();

      // dt partial + warp reduce
      {
        float a = __fmul_rn(hb[2 * tid], SM[OFF_WTM + 2 * tid]);
        a = fmaf(hb[2 * tid + 1], SM[OFF_WTM + 2 * tid + 1], a);
        for (int o = 16; o; o >>= 1)
          a = __fadd_rn(a, __shfl_down_sync(0xffffffffu, a, o));
        if (lane == 0) red[warp] = a;
      }
      __syncthreads();

      // neighbor scores
      for (int k = warp; k < Kk; k += 8) {
        const float* ev = sE + k * 256;
        float acc = 0.0f;
        for (int i = lane; i < Ek + Dk; i += 32) {
          float v = (i < Ek) ? ev[i] : hb[i - Ek];
          acc = fmaf(v, SM[OFF_WMK + i], acc);
        }
        for (int o = 16; o; o >>= 1) acc += __shfl_down_sync(0xffffffffu, acc, o);
        if (lane == 0) s_score[k] = __fadd_rn(acc, SM[OFF_BT + 1]);
      }

      float newt = 0.0f;
      if (tid == 0) {
        float s = red[0];
        for (int w = 1; w < 8; w++) s = __fadd_rn(s, red[w]);
        float xx = __fadd_rn(s, SM[OFF_BT]);
        float sp = __fadd_rn(fmaxf(xx, 0.0f), log1pf(expf(-fabsf(xx))));
        newt = __fadd_rn(SM[OFF_BT + 2], sp);
      }
      __syncthreads();

      // softmax + prob/cand update on warp 0 (lanes 0..15)
      if (warp == 0) {
        float sc = (lane < Kk) ? s_score[lane] : -3.4e38f;
        float mx = sc;
        for (int o = 8; o; o >>= 1)
          mx = fmaxf(mx, __shfl_xor_sync(0xffffffffu, mx, o));  // exact max
        float ek = (lane < Kk) ? expf(__fadd_rn(sc, -mx)) : 0.0f;
        float ssum = 0.0f;
#pragma unroll
        for (int k = 0; k < Kk; k++)
          ssum = __fadd_rn(ssum, __shfl_sync(0xffffffffu, ek, k));
        float cp = sP[chosen];
        __syncwarp();
        if (lane < Kk) {
          float att = __fmul_rn(cp, __fdiv_rn(ek, ssum));
          if (lane == 0) {
            sP[chosen] = att;
          } else {
            int base = 1 + t * (Kk - 1);
            sP[base + lane - 1] = att;
            sC[base + lane - 1] = s_neigh[lane];
          }
        }
      }
      __syncthreads();

      // gumbel-max over the active prefix
      uint32_t k0, k1;
      tf2x32(0u, 42u, 0u, (uint32_t)t, k0, k1);
      int active = 15 * t + 16;
      if (active > Lk) active = Lk;
      float bv = -3.4e38f; int bi = 0x7fffffff;
      for (int l = tid; l < active; l += 256) {
        float pr = sP[l];
        float logit = (pr > 0.0f) ? logf(fmaxf(pr, 1e-38f)) : -1e30f;
        uint32_t i = (uint32_t)(myb * Lk + l);
        uint32_t o0, o1;
        tf2x32(k0, k1, 0u, i, o0, o1);
        uint32_t bits = o0 ^ o1;
        float u0 = __fadd_rn(__uint_as_float((bits >> 9) | 0x3f800000u), -1.0f);
        float u = fmaxf(TINYF, __fadd_rn(u0, TINYF));
        float gq = -logf(-logf(u));
        float v = __fadd_rn(logit, gq);
        if (v > bv) { bv = v; bi = l; }
      }
      for (int o = 16; o; o >>= 1) {
        float ov = __shfl_down_sync(0xffffffffu, bv, o);
        int   oi = __shfl_down_sync(0xffffffffu, bi, o);
        if (ov > bv || (ov == bv && oi < bi)) { bv = ov; bi = oi; }
      }
      if (lane == 0) { redv[warp] = bv; ri[warp] = bi; }
      __syncthreads();

      float bestv = redv[0]; int besti = ri[0];
      for (int w = 1; w < 8; w++) {
        if (redv[w] > bestv || (redv[w] == bestv && ri[w] < besti)) {
          bestv = redv[w]; besti = ri[w];
        }
      }
      chosen = besti;
      if (tid == 0) {
        int nm = sC[besti];
        int col = t + 1;
        out[0 * 16384 + myb * Sk + col] = (float)nm;
        out[1 * 16384 + myb * Sk + col] = newt;
        out[2 * 16384 + myb * Sk + col] = (newt < 1000.0f) ? 1.0f : 0.0f;
        out[3 * 16384 + myb * Sk + col] = sN[besti];
        out[4 * 16384 + myb * Sk + col] = sP[besti];
        SM[OFF_BT + 2] = newt;
        __stcg(&g_last_m[myb], nm);
        __stcg(&g_last_t[myb], newt);
      }
    }
    gbar(bc, epoch);
  }
#undef STAGE
#undef CHUNK
}

extern "C" void kernel_launch(void* const* d_in, const int* in_sizes, int n_in,
                              void* d_out, int out_size) {
  const int*   marker = (const int*)d_in[0];
  const float* timed  = (const float*)d_in[1];
  const float* maskd  = (const float*)d_in[2];
  const float* emb    = (const float*)d_in[3];
  const int*   nlist  = (const int*)d_in[4];
  const float* nprob  = (const float*)d_in[5];
  const float* W_te   = (const float*)d_in[6];
  const float* b_te   = (const float*)d_in[7];
  const float* W_el   = (const float*)d_in[8];
  const float* b_el   = (const float*)d_in[9];
  const float* W_ih   = (const float*)d_in[10];
  const float* b_ih   = (const float*)d_in[11];
  const float* W_hh   = (const float*)d_in[12];
  const float* b_hh   = (const float*)d_in[13];
  const float* W_time = (const float*)d_in[14];
  const float* b_time = (const float*)d_in[15];
  const float* W_mk   = (const float*)d_in[16];
  const float* b_mk   = (const float*)d_in[17];
  float* out = (float*)d_out;

  cudaFuncSetAttribute(rnn_persistent,
                       cudaFuncAttributeMaxDynamicSharedMemorySize, SM_BYTES);
  reset_kernel<<<1, 1024>>>();
  rnn_persistent<<<148, 256, SM_BYTES>>>(marker, timed, maskd, emb, nlist, nprob,
                                         W_te, b_te, W_el, b_el, W_ih, b_ih,
                                         W_hh, b_hh, W_time, b_time, W_mk, b_mk,
                                         out);
}

// round 10
// speedup vs baseline: 1.0513x; 1.0513x over previous
#include <cuda_runtime.h>
#include <cstdint>

#define Bk 128
#define Sk 128
#define Ek 256
#define Dk 512
#define Kk 16
#define Lk 1906
#define Rk 2033
#define Tk 127
#define TINYF 1.17549435e-38f

// smem layout (float offsets)
#define OFF_STA   0        // buffer A: 32x260
#define OFF_STB   8320     // buffer B: 32x260
#define OFF_WA    16640    // W_el tile: 256e x 8dp float2
#define OFF_WBI   20736    // 8dp x 514 float2
#define OFF_WBH   28960
#define OFF_SE    37184    // 16x256 neighbor emb
#define OFF_WMK   41280    // 768
#define OFF_WTM   42048    // 512
#define OFF_WTE   42560    // 256
#define OFF_BTE   42816    // 256
#define OFF_BEL   43072    // 512
#define OFF_BIH   43584    // 512
#define OFF_BHH   44096    // 512
#define OFF_BT    44608    // b_time, b_mk, last_t_my
#define OFF_SLT   44612    // 32
#define OFF_SLM   44644    // 32
#define OFF_CS    44676    // red8, redv8, ri8, neigh16, score16
#define OFF_SP    44740    // prob[1906]
#define OFF_SC    46646    // cand[1906] (int)
#define OFF_SN    48552    // nrec[2033]
#define SM_FLOATS 50592
#define SM_BYTES  (SM_FLOATS * 4)

__device__ float g_h[2][Bk][Dk];
__device__ float g_x[Bk][Dk];
__device__ float g_last_t[Bk];
__device__ int   g_last_m[Bk];
__device__ unsigned g_cnt[4][32];   // per-group counters, 128B apart

// JAX threefry2x32 (exact)
__device__ __forceinline__ void tf2x32(uint32_t k0, uint32_t k1,
                                       uint32_t x0, uint32_t x1,
                                       uint32_t& o0, uint32_t& o1) {
  uint32_t ks2 = k0 ^ k1 ^ 0x1BD11BDAu;
  x0 += k0; x1 += k1;
#define RR(d) { x0 += x1; x1 = (x1 << d) | (x1 >> (32 - d)); x1 ^= x0; }
  RR(13) RR(15) RR(26) RR(6)  x0 += k1;  x1 += ks2 + 1u;
  RR(17) RR(29) RR(16) RR(24) x0 += ks2; x1 += k0 + 2u;
  RR(13) RR(15) RR(26) RR(6)  x0 += k0;  x1 += k1 + 3u;
  RR(17) RR(29) RR(16) RR(24) x0 += k1;  x1 += ks2 + 4u;
  RR(13) RR(15) RR(26) RR(6)  x0 += ks2; x1 += k0 + 5u;
#undef RR
  o0 = x0; o1 = x1;
}

__device__ __forceinline__ unsigned long long dup2(float v) {
  unsigned long long r;
  asm("mov.b64 %0, {%1, %1};" : "=l"(r) : "f"(v));
  return r;
}
__device__ __forceinline__ void ffma2(unsigned long long& acc,
                                      unsigned long long a,
                                      unsigned long long b) {
  asm("fma.rn.f32x2 %0, %1, %2, %3;" : "=l"(acc) : "l"(a), "l"(b), "l"(acc));
}
__device__ __forceinline__ unsigned long long add2(unsigned long long a,
                                                   unsigned long long b) {
  unsigned long long r;
  asm("add.rn.f32x2 %0, %1, %2;" : "=l"(r) : "l"(a), "l"(b));
  return r;
}
__device__ __forceinline__ void cpa16(uint32_t s, const void* g) {
  asm volatile("cp.async.cg.shared.global [%0], [%1], 16;"
               :: "r"(s), "l"(g) : "memory");
}
__device__ __forceinline__ void cpa_commit() {
  asm volatile("cp.async.commit_group;" ::: "memory");
}
template <int N>
__device__ __forceinline__ void cpa_wait_group() {
  asm volatile("cp.async.wait_group %0;" :: "n"(N) : "memory");
}

__global__ void reset_kernel() {
  if (threadIdx.x < 128) ((unsigned*)g_cnt)[threadIdx.x] = 0u;
}

// R8-proven barrier: release-red arrive + volatile poll on counter
__device__ __forceinline__ void gbar(int bc, unsigned& epoch) {
  __syncthreads();
  if (threadIdx.x == 0) {
    epoch += 32u;
    asm volatile("red.release.gpu.global.add.u32 [%0], %1;"
                 :: "l"(&g_cnt[bc][0]), "r"(1u) : "memory");
    while (*((volatile unsigned*)&g_cnt[bc][0]) < epoch) { }
  }
  __syncthreads();
}

__global__ void __launch_bounds__(256, 1)
rnn_persistent(const int* __restrict__ marker,
               const float* __restrict__ timed,
               const float* __restrict__ maskd,
               const float* __restrict__ emb,
               const int* __restrict__ nlist,
               const float* __restrict__ nprob,
               const float* __restrict__ W_te,
               const float* __restrict__ b_te,
               const float* __restrict__ W_el,
               const float* __restrict__ b_el,
               const float* __restrict__ W_ih,
               const float* __restrict__ b_ih,
               const float* __restrict__ W_hh,
               const float* __restrict__ b_hh,
               const float* __restrict__ W_time,
               const float* __restrict__ b_time,
               const float* __restrict__ W_mk,
               const float* __restrict__ b_mk,
               float* __restrict__ out) {
  extern __shared__ __align__(16) float SM[];
  const int BID = blockIdx.x;
  if (BID >= 128) return;
  const int tid = threadIdx.x;
  const int bc = BID >> 5;           // group (32 batch rows)
  const int dc = BID & 31;           // d tile (16 cols)
  const int myb = BID;               // phase-C row
  unsigned epoch = 0;

  float* sP = SM + OFF_SP;
  int*   sC = (int*)(SM + OFF_SC);
  float* sN = SM + OFF_SN;

  // ---------------- one-time init ----------------
  for (int i = tid; i < Ek * 8; i += 256) {
    int e = i >> 3, dp8 = i & 7;
    ((float2*)(SM + OFF_WA))[e * 8 + dp8] =
        *(const float2*)&W_el[e * Dk + dc * 16 + dp8 * 2];
  }
  for (int i = tid; i < Dk * 8; i += 256) {
    int e = i >> 3, dp8 = i & 7;
    ((float2*)(SM + OFF_WBI))[dp8 * 514 + e] =
        *(const float2*)&W_ih[e * Dk + dc * 16 + dp8 * 2];
    ((float2*)(SM + OFF_WBH))[dp8 * 514 + e] =
        *(const float2*)&W_hh[e * Dk + dc * 16 + dp8 * 2];
  }
  for (int i = tid; i < Ek + Dk; i += 256) SM[OFF_WMK + i] = W_mk[i];
  for (int i = tid; i < Dk; i += 256) {
    SM[OFF_WTM + i] = W_time[i];
    SM[OFF_BEL + i] = b_el[i];
    SM[OFF_BIH + i] = b_ih[i];
    SM[OFF_BHH + i] = b_hh[i];
  }
  if (tid < Ek) { SM[OFF_WTE + tid] = W_te[tid]; SM[OFF_BTE + tid] = b_te[tid]; }
  if (tid == 0) {
    SM[OFF_BT] = b_time[0]; SM[OFF_BT + 1] = b_mk[0];
    SM[OFF_BT + 2] = timed[myb * Sk];        // last_t (own row)
  }
  for (int l = tid; l < Lk; l += 256) {
    sP[l] = (l == 0) ? 1.0f : 0.0f;
    sC[l] = (l == 0) ? marker[myb * Sk] : 0;
  }
  for (int r = tid; r < Rk; r += 256) sN[r] = 1.0f;
  for (int d = tid; d < Dk; d += 256) __stcg(&g_h[0][myb][d], 0.0f);
  int chosen = 0;
  if (tid == 0) {
    __stcg(&g_last_t[myb], timed[myb * Sk]);
    __stcg(&g_last_m[myb], marker[myb * Sk]);
    out[0 * 16384 + myb * Sk] = (float)marker[myb * Sk];
    out[1 * 16384 + myb * Sk] = timed[myb * Sk];
    out[2 * 16384 + myb * Sk] = maskd[myb * Sk];
    out[3 * 16384 + myb * Sk] = 1.0f;
    out[4 * 16384 + myb * Sk] = 1.0f;
  }
  gbar(bc, epoch);

  const int dp = tid & 7;
  const int blw = tid >> 3;          // 0..31
  const int d0 = dc * 16 + dp * 2;
  const int bg = bc * 32 + blw;
  int*   s_neigh = (int*)(SM + OFF_CS + 24);
  float* s_score = SM + OFF_CS + 40;
  const uint32_t stA = (uint32_t)__cvta_generic_to_shared(SM + OFF_STA);
  const uint32_t stB = (uint32_t)__cvta_generic_to_shared(SM + OFF_STB);
  const uint32_t se_base = (uint32_t)__cvta_generic_to_shared(SM + OFF_SE);

#define STAGE(gptr, ebase, dst)                                           \
  {                                                                       \
    _Pragma("unroll")                                                     \
    for (int j = 0; j < 8; j++) {                                         \
      int id = tid + j * 256;                                             \
      int rr = id >> 6, seg = id & 63;                                    \
      cpa16((dst) + (uint32_t)(rr * 260 + seg * 4) * 4,                   \
            (gptr) + (size_t)(bc * 32 + rr) * Dk + (ebase) + seg * 4);    \
    }                                                                     \
    cpa_commit();                                                         \
  }
  // 4-accumulator chunk: float4 lane -> own accumulator (chain /4)
#define CHUNK(accA, wbase, half, buf)                                     \
  {                                                                       \
    const float4* pxc = (const float4*)(SM + (buf) + blw * 260);          \
    const ulonglong2* pw =                                                \
        (const ulonglong2*)(SM + (wbase)) + dp * 257 + (half) * 128;      \
    _Pragma("unroll 8")                                                   \
    for (int e4 = 0; e4 < 64; e4++) {                                     \
      float4 q = pxc[e4];                                                 \
      ulonglong2 wA = pw[2 * e4], wB = pw[2 * e4 + 1];                    \
      ffma2(accA[0], dup2(q.x), wA.x);                                    \
      ffma2(accA[1], dup2(q.y), wA.y);                                    \
      ffma2(accA[2], dup2(q.z), wB.x);                                    \
      ffma2(accA[3], dup2(q.w), wB.y);                                    \
    }                                                                     \
  }

  for (int t = 0; t < Tk; t++) {
    const float* hin = &g_h[t & 1][0][0];
    // ============ Phase A: x = leaky(vec @ W_el + b_el) ============
    {
      if (tid < 32) {
        SM[OFF_SLT + tid] = __ldcg(&g_last_t[bc * 32 + tid]);
        ((int*)(SM + OFF_SLM))[tid] = __ldcg(&g_last_m[bc * 32 + tid]);
      }
      __syncthreads();
#pragma unroll
      for (int j = 0; j < 8; j++) {
        int id = tid + j * 256;
        int bl = id >> 6, seg = id & 63;
        cpa16(stA + (uint32_t)(bl * 260 + seg * 4) * 4,
              emb + (size_t)((int*)(SM + OFF_SLM))[bl] * Ek + seg * 4);
      }
      cpa_commit();
      cpa_wait_group<0>();
      __syncthreads();
      {
        float wte = SM[OFF_WTE + tid], bte = SM[OFF_BTE + tid];
        float* sV = SM + OFF_STA;
#pragma unroll 4
        for (int bl = 0; bl < 32; bl++) {
          float te = __fadd_rn(__fmul_rn(SM[OFF_SLT + bl], wte), bte);
          sV[bl * 260 + tid] = __fadd_rn(sV[bl * 260 + tid], __fmul_rn(0.1f, te));
        }
      }
      __syncthreads();
      const float4* pv4 = (const float4*)(SM + OFF_STA + blw * 260);
      const unsigned long long* wa = (const unsigned long long*)(SM + OFF_WA);
      unsigned long long acc[4] = {0ull, 0ull, 0ull, 0ull};
#pragma unroll 8
      for (int e4 = 0; e4 < Ek / 4; e4++) {
        float4 q = pv4[e4];
        ffma2(acc[0], dup2(q.x), wa[(e4 * 4 + 0) * 8 + dp]);
        ffma2(acc[1], dup2(q.y), wa[(e4 * 4 + 1) * 8 + dp]);
        ffma2(acc[2], dup2(q.z), wa[(e4 * 4 + 2) * 8 + dp]);
        ffma2(acc[3], dup2(q.w), wa[(e4 * 4 + 3) * 8 + dp]);
      }
      unsigned long long accT = add2(add2(acc[0], acc[1]), add2(acc[2], acc[3]));
      float a0, a1;
      asm("mov.b64 {%0, %1}, %2;" : "=f"(a0), "=f"(a1) : "l"(accT));
      a0 = __fadd_rn(a0, SM[OFF_BEL + d0]);
      a1 = __fadd_rn(a1, SM[OFF_BEL + d0 + 1]);
      float2 r;
      r.x = (a0 >= 0.0f) ? a0 : __fmul_rn(0.01f, a0);
      r.y = (a1 >= 0.0f) ? a1 : __fmul_rn(0.01f, a1);
      __stcg((float2*)&g_x[bg][d0], r);

      // prefetch C's neighbor rows (overlaps phase B)
      int lm_my = ((int*)(SM + OFF_SLM))[dc];
      if (tid < Kk) {
        s_neigh[tid] = nlist[lm_my * Kk + tid];
        sN[1 + t * Kk + tid] = nprob[lm_my * Kk + tid];
      }
      __syncthreads();
#pragma unroll
      for (int j = 0; j < 4; j++) {
        int id = tid + j * 256;
        int k = id >> 6, seg = id & 63;
        cpa16(se_base + (uint32_t)(k * 256 + seg * 4) * 4,
              emb + (size_t)s_neigh[k] * Ek + seg * 4);
      }
      cpa_commit();
    }
    gbar(bc, epoch);

    // ==== Phase B: pipelined h = tanh(x@Wih + b + h@Whh + b) ====
    {
      unsigned long long axx[4] = {0ull, 0ull, 0ull, 0ull};
      unsigned long long ahh[4] = {0ull, 0ull, 0ull, 0ull};
      STAGE(&g_x[0][0], 0, stA)        // [SE, x0]
      STAGE(&g_x[0][0], 256, stB)      // [SE, x0, x1]
      cpa_wait_group<1>();             // SE, x0 done
      __syncthreads();
      CHUNK(axx, OFF_WBI, 0, OFF_STA)
      __syncthreads();
      STAGE(hin, 0, stA)               // [x1, h0]
      cpa_wait_group<1>();             // x1 done
      __syncthreads();
      CHUNK(axx, OFF_WBI, 1, OFF_STB)
      __syncthreads();
      STAGE(hin, 256, stB)             // [h0, h1]
      cpa_wait_group<1>();             // h0 done
      __syncthreads();
      CHUNK(ahh, OFF_WBH, 0, OFF_STA)
      cpa_wait_group<0>();             // h1 done
      __syncthreads();
      CHUNK(ahh, OFF_WBH, 1, OFF_STB)

      unsigned long long axT = add2(add2(axx[0], axx[1]), add2(axx[2], axx[3]));
      unsigned long long ahT = add2(add2(ahh[0], ahh[1]), add2(ahh[2], ahh[3]));
      float ax0, ax1, ah0, ah1;
      asm("mov.b64 {%0, %1}, %2;" : "=f"(ax0), "=f"(ax1) : "l"(axT));
      asm("mov.b64 {%0, %1}, %2;" : "=f"(ah0), "=f"(ah1) : "l"(ahT));
      float2 r;
      r.x = tanhf(__fadd_rn(__fadd_rn(__fadd_rn(ax0, SM[OFF_BIH + d0]), ah0),
                            SM[OFF_BHH + d0]));
      r.y = tanhf(__fadd_rn(__fadd_rn(__fadd_rn(ax1, SM[OFF_BIH + d0 + 1]), ah1),
                            SM[OFF_BHH + d0 + 1]));
      __stcg((float2*)&g_h[(t + 1) & 1][bg][d0], r);
    }
    gbar(bc, epoch);

    // ============ Phase C: sampling step for row myb ============
    {
      float* hb   = SM + OFF_STA;           // [512]
      float* red  = SM + OFF_CS;            // [8]
      float* redv = SM + OFF_CS + 8;        // [8]
      int*   ri   = (int*)(SM + OFF_CS + 16);
      float* sE   = SM + OFF_SE;
      int warp = tid >> 5, lane = tid & 31;

      hb[tid]       = __ldcg(&g_h[(t + 1) & 1][myb][tid]);
      hb[tid + 256] = __ldcg(&g_h[(t + 1) & 1][myb][tid + 256]);
      __syncthreads();

      // dt partial + warp reduce
      {
        float a = __fmul_rn(hb[2 * tid], SM[OFF_WTM + 2 * tid]);
        a = fmaf(hb[2 * tid + 1], SM[OFF_WTM + 2 * tid + 1], a);
        for (int o = 16; o; o >>= 1)
          a = __fadd_rn(a, __shfl_down_sync(0xffffffffu, a, o));
        if (lane == 0) red[warp] = a;
      }
      __syncthreads();

      // neighbor scores: 2-accumulator chains
      for (int k = warp; k < Kk; k += 8) {
        const float* ev = sE + k * 256;
        float acc0 = 0.0f, acc1 = 0.0f;
#pragma unroll
        for (int i = lane; i < Ek + Dk; i += 64) {
          float v0 = (i < Ek) ? ev[i] : hb[i - Ek];
          int i2 = i + 32;
          float v1 = (i2 < Ek) ? ev[i2] : hb[i2 - Ek];
          acc0 = fmaf(v0, SM[OFF_WMK + i], acc0);
          acc1 = fmaf(v1, SM[OFF_WMK + i2], acc1);
        }
        float acc = __fadd_rn(acc0, acc1);
        for (int o = 16; o; o >>= 1) acc += __shfl_down_sync(0xffffffffu, acc, o);
        if (lane == 0) s_score[k] = __fadd_rn(acc, SM[OFF_BT + 1]);
      }

      float newt = 0.0f;
      if (tid == 0) {
        float s = red[0];
        for (int w = 1; w < 8; w++) s = __fadd_rn(s, red[w]);
        float xx = __fadd_rn(s, SM[OFF_BT]);
        float sp = __fadd_rn(fmaxf(xx, 0.0f), log1pf(expf(-fabsf(xx))));
        newt = __fadd_rn(SM[OFF_BT + 2], sp);
      }
      __syncthreads();

      // softmax + prob/cand update on warp 0 (lanes 0..15)
      if (warp == 0) {
        float sc = (lane < Kk) ? s_score[lane] : -3.4e38f;
        float mx = sc;
        for (int o = 8; o; o >>= 1)
          mx = fmaxf(mx, __shfl_xor_sync(0xffffffffu, mx, o));
        float ek = (lane < Kk) ? expf(__fadd_rn(sc, -mx)) : 0.0f;
        float ssum = 0.0f;
#pragma unroll
        for (int k = 0; k < Kk; k++)
          ssum = __fadd_rn(ssum, __shfl_sync(0xffffffffu, ek, k));
        float cp = sP[chosen];
        __syncwarp();
        if (lane < Kk) {
          float att = __fmul_rn(cp, __fdiv_rn(ek, ssum));
          if (lane == 0) {
            sP[chosen] = att;
          } else {
            int base = 1 + t * (Kk - 1);
            sP[base + lane - 1] = att;
            sC[base + lane - 1] = s_neigh[lane];
          }
        }
      }
      __syncthreads();

      // gumbel-max over the active prefix
      uint32_t k0, k1;
      tf2x32(0u, 42u, 0u, (uint32_t)t, k0, k1);
      int active = 15 * t + 16;
      if (active > Lk) active = Lk;
      float bv = -3.4e38f; int bi = 0x7fffffff;
      for (int l = tid; l < active; l += 256) {
        float pr = sP[l];
        float logit = (pr > 0.0f) ? logf(fmaxf(pr, 1e-38f)) : -1e30f;
        uint32_t i = (uint32_t)(myb * Lk + l);
        uint32_t o0, o1;
        tf2x32(k0, k1, 0u, i, o0, o1);
        uint32_t bits = o0 ^ o1;
        float u0 = __fadd_rn(__uint_as_float((bits >> 9) | 0x3f800000u), -1.0f);
        float u = fmaxf(TINYF, __fadd_rn(u0, TINYF));
        float gq = -logf(-logf(u));
        float v = __fadd_rn(logit, gq);
        if (v > bv) { bv = v; bi = l; }
      }
      for (int o = 16; o; o >>= 1) {
        float ov = __shfl_down_sync(0xffffffffu, bv, o);
        int   oi = __shfl_down_sync(0xffffffffu, bi, o);
        if (ov > bv || (ov == bv && oi < bi)) { bv = ov; bi = oi; }
      }
      if (lane == 0) { redv[warp] = bv; ri[warp] = bi; }
      __syncthreads();

      float bestv = redv[0]; int besti = ri[0];
      for (int w = 1; w < 8; w++) {
        if (redv[w] > bestv || (redv[w] == bestv && ri[w] < besti)) {
          bestv = redv[w]; besti = ri[w];
        }
      }
      chosen = besti;
      if (tid == 0) {
        int nm = sC[besti];
        int col = t + 1;
        out[0 * 16384 + myb * Sk + col] = (float)nm;
        out[1 * 16384 + myb * Sk + col] = newt;
        out[2 * 16384 + myb * Sk + col] = (newt < 1000.0f) ? 1.0f : 0.0f;
        out[3 * 16384 + myb * Sk + col] = sN[besti];
        out[4 * 16384 + myb * Sk + col] = sP[besti];
        SM[OFF_BT + 2] = newt;
        __stcg(&g_last_m[myb], nm);
        __stcg(&g_last_t[myb], newt);
      }
    }
    gbar(bc, epoch);
  }
#undef STAGE
#undef CHUNK
}

extern "C" void kernel_launch(void* const* d_in, const int* in_sizes, int n_in,
                              void* d_out, int out_size) {
  const int*   marker = (const int*)d_in[0];
  const float* timed  = (const float*)d_in[1];
  const float* maskd  = (const float*)d_in[2];
  const float* emb    = (const float*)d_in[3];
  const int*   nlist  = (const int*)d_in[4];
  const float* nprob  = (const float*)d_in[5];
  const float* W_te   = (const float*)d_in[6];
  const float* b_te   = (const float*)d_in[7];
  const float* W_el   = (const float*)d_in[8];
  const float* b_el   = (const float*)d_in[9];
  const float* W_ih   = (const float*)d_in[10];
  const float* b_ih   = (const float*)d_in[11];
  const float* W_hh   = (const float*)d_in[12];
  const float* b_hh   = (const float*)d_in[13];
  const float* W_time = (const float*)d_in[14];
  const float* b_time = (const float*)d_in[15];
  const float* W_mk   = (const float*)d_in[16];
  const float* b_mk   = (const float*)d_in[17];
  float* out = (float*)d_out;

  cudaFuncSetAttribute(rnn_persistent,
                       cudaFuncAttributeMaxDynamicSharedMemorySize, SM_BYTES);
  reset_kernel<<<1, 128>>>();
  rnn_persistent<<<148, 256, SM_BYTES>>>(marker, timed, maskd, emb, nlist, nprob,
                                         W_te, b_te, W_el, b_el, W_ih, b_ih,
                                         W_hh, b_hh, W_time, b_time, W_mk, b_mk,
                                         out);
}

// round 12
// speedup vs baseline: 1.0716x; 1.0193x over previous
#include <cuda_runtime.h>
#include <cstdint>

#define Bk 128
#define Sk 128
#define Ek 256
#define Dk 512
#define Kk 16
#define Lk 1906
#define Rk 2033
#define Tk 127
#define TINYF 1.17549435e-38f

// smem layout (float offsets)
#define OFF_BUFA  0        // 32x260
#define OFF_BUFB  8320     // 32x260
#define OFF_BUFC  16640    // 32x260
#define OFF_WA    24960    // 256e x 8dp float2 = 4096
#define OFF_WBI   29056    // 8dp x 514 float2 = 8224
#define OFF_WBH   37280    // 8224
#define OFF_SE    45504    // 16x256 = 4096
#define OFF_WMK   49600    // 768
#define OFF_WTM   50368    // 512
#define OFF_WTE   50880    // 256
#define OFF_BTE   51136    // 256
#define OFF_BEL   51392    // 512
#define OFF_BIH   51904    // 512
#define OFF_BHH   52416    // 512
#define OFF_BT    52928    // 4: b_time, b_mk, last_t_my
#define OFF_SLT   52932    // 32
#define OFF_SLM   52964    // 32
#define OFF_CS    52996    // red16, redv16, ri16, neigh16, score16 = 80
#define OFF_CMB   53076    // 256 float2 = 512
#define OFF_SP    53588    // prob[1906]
#define SM_FLOATS 55494
#define SM_BYTES  (SM_FLOATS * 4)

__device__ float g_h[2][Bk][Dk];
__device__ float g_x[Bk][Dk];
__device__ float g_last_t[Bk];
__device__ int   g_last_m[Bk];
__device__ int   g_cand[Bk][Lk];
__device__ float g_nrec[Bk][Rk];
__device__ unsigned g_cnt[4][32];

// JAX threefry2x32 (exact)
__device__ __forceinline__ void tf2x32(uint32_t k0, uint32_t k1,
                                       uint32_t x0, uint32_t x1,
                                       uint32_t& o0, uint32_t& o1) {
  uint32_t ks2 = k0 ^ k1 ^ 0x1BD11BDAu;
  x0 += k0; x1 += k1;
#define RR(d) { x0 += x1; x1 = (x1 << d) | (x1 >> (32 - d)); x1 ^= x0; }
  RR(13) RR(15) RR(26) RR(6)  x0 += k1;  x1 += ks2 + 1u;
  RR(17) RR(29) RR(16) RR(24) x0 += ks2; x1 += k0 + 2u;
  RR(13) RR(15) RR(26) RR(6)  x0 += k0;  x1 += k1 + 3u;
  RR(17) RR(29) RR(16) RR(24) x0 += k1;  x1 += ks2 + 4u;
  RR(13) RR(15) RR(26) RR(6)  x0 += ks2; x1 += k0 + 5u;
#undef RR
  o0 = x0; o1 = x1;
}

__device__ __forceinline__ unsigned long long dup2(float v) {
  unsigned long long r;
  asm("mov.b64 %0, {%1, %1};" : "=l"(r) : "f"(v));
  return r;
}
__device__ __forceinline__ void ffma2(unsigned long long& acc,
                                      unsigned long long a,
                                      unsigned long long b) {
  asm("fma.rn.f32x2 %0, %1, %2, %3;" : "=l"(acc) : "l"(a), "l"(b), "l"(acc));
}
__device__ __forceinline__ unsigned long long add2(unsigned long long a,
                                                   unsigned long long b) {
  unsigned long long r;
  asm("add.rn.f32x2 %0, %1, %2;" : "=l"(r) : "l"(a), "l"(b));
  return r;
}
__device__ __forceinline__ void cpa16(uint32_t s, const void* g) {
  asm volatile("cp.async.cg.shared.global [%0], [%1], 16;"
               :: "r"(s), "l"(g) : "memory");
}
__device__ __forceinline__ void cpa_commit() {
  asm volatile("cp.async.commit_group;" ::: "memory");
}
template <int N>
__device__ __forceinline__ void cpa_wait_group() {
  asm volatile("cp.async.wait_group %0;" :: "n"(N) : "memory");
}
// half-scoped named barriers (256 threads each)
__device__ __forceinline__ void hbar(int id) {
  asm volatile("bar.sync %0, 256;" :: "r"(id) : "memory");
}

__global__ void reset_kernel() {
  if (threadIdx.x < 128) ((unsigned*)g_cnt)[threadIdx.x] = 0u;
}

// R8-proven barrier: release-red arrive + volatile poll on counter
__device__ __forceinline__ void gbar(int bc, unsigned& epoch) {
  __syncthreads();
  if (threadIdx.x == 0) {
    epoch += 32u;
    asm volatile("red.release.gpu.global.add.u32 [%0], %1;"
                 :: "l"(&g_cnt[bc][0]), "r"(1u) : "memory");
    while (*((volatile unsigned*)&g_cnt[bc][0]) < epoch) { }
  }
  __syncthreads();
}

__global__ void __launch_bounds__(512, 1)
rnn_persistent(const int* __restrict__ marker,
               const float* __restrict__ timed,
               const float* __restrict__ maskd,
               const float* __restrict__ emb,
               const int* __restrict__ nlist,
               const float* __restrict__ nprob,
               const float* __restrict__ W_te,
               const float* __restrict__ b_te,
               const float* __restrict__ W_el,
               const float* __restrict__ b_el,
               const float* __restrict__ W_ih,
               const float* __restrict__ b_ih,
               const float* __restrict__ W_hh,
               const float* __restrict__ b_hh,
               const float* __restrict__ W_time,
               const float* __restrict__ b_time,
               const float* __restrict__ W_mk,
               const float* __restrict__ b_mk,
               float* __restrict__ out) {
  extern __shared__ __align__(16) float SM[];
  const int BID = blockIdx.x;
  if (BID >= 128) return;
  const int tid = threadIdx.x;
  const int bc = BID >> 5;           // group (32 batch rows)
  const int dc = BID & 31;           // d tile (16 cols)
  const int myb = BID;
  unsigned epoch = 0;

  float* sP = SM + OFF_SP;

  // ---------------- one-time init ----------------
  for (int i = tid; i < Ek * 8; i += 512) {
    int e = i >> 3, dp8 = i & 7;
    ((float2*)(SM + OFF_WA))[e * 8 + dp8] =
        *(const float2*)&W_el[e * Dk + dc * 16 + dp8 * 2];
  }
  for (int i = tid; i < Dk * 8; i += 512) {
    int e = i >> 3, dp8 = i & 7;
    ((float2*)(SM + OFF_WBI))[dp8 * 514 + e] =
        *(const float2*)&W_ih[e * Dk + dc * 16 + dp8 * 2];
    ((float2*)(SM + OFF_WBH))[dp8 * 514 + e] =
        *(const float2*)&W_hh[e * Dk + dc * 16 + dp8 * 2];
  }
  for (int i = tid; i < Ek + Dk; i += 512) SM[OFF_WMK + i] = W_mk[i];
  if (tid < Dk) {
    SM[OFF_WTM + tid] = W_time[tid];
    SM[OFF_BEL + tid] = b_el[tid];
    SM[OFF_BIH + tid] = b_ih[tid];
    SM[OFF_BHH + tid] = b_hh[tid];
  }
  if (tid < Ek) { SM[OFF_WTE + tid] = W_te[tid]; SM[OFF_BTE + tid] = b_te[tid]; }
  if (tid == 0) {
    SM[OFF_BT] = b_time[0]; SM[OFF_BT + 1] = b_mk[0];
    SM[OFF_BT + 2] = timed[myb * Sk];
  }
  for (int l = tid; l < Lk; l += 512) {
    sP[l] = (l == 0) ? 1.0f : 0.0f;
    g_cand[myb][l] = (l == 0) ? marker[myb * Sk] : 0;
  }
  for (int r = tid; r < Rk; r += 512) g_nrec[myb][r] = 1.0f;
  for (int d = tid; d < Dk; d += 512) __stcg(&g_h[0][myb][d], 0.0f);
  int chosen = 0;
  if (tid == 0) {
    __stcg(&g_last_t[myb], timed[myb * Sk]);
    __stcg(&g_last_m[myb], marker[myb * Sk]);
    out[0 * 16384 + myb * Sk] = (float)marker[myb * Sk];
    out[1 * 16384 + myb * Sk] = timed[myb * Sk];
    out[2 * 16384 + myb * Sk] = maskd[myb * Sk];
    out[3 * 16384 + myb * Sk] = 1.0f;
    out[4 * 16384 + myb * Sk] = 1.0f;
  }
  gbar(bc, epoch);

  const int half = tid >> 8;          // 0: x-part, 1: h-part
  const int htid = tid & 255;
  const int dp = htid & 7;
  const int blw = htid >> 3;          // 0..31
  const int d0 = dc * 16 + dp * 2;
  const int bg = bc * 32 + blw;
  const int warp = tid >> 5, lane = tid & 31;
  int*   s_neigh = (int*)(SM + OFF_CS + 48);
  float* s_score = SM + OFF_CS + 64;
  unsigned long long* sCMB = (unsigned long long*)(SM + OFF_CMB);
  const uint32_t stA = (uint32_t)__cvta_generic_to_shared(SM + OFF_BUFA);
  const uint32_t stB = (uint32_t)__cvta_generic_to_shared(SM + OFF_BUFB);
  const uint32_t stC = (uint32_t)__cvta_generic_to_shared(SM + OFF_BUFC);
  const uint32_t se_base = (uint32_t)__cvta_generic_to_shared(SM + OFF_SE);

#define STAGE_H(gptr, ebase, dst)                                         \
  {                                                                       \
    _Pragma("unroll")                                                     \
    for (int j = 0; j < 8; j++) {                                         \
      int id = htid + j * 256;                                            \
      int rr = id >> 6, seg = id & 63;                                    \
      cpa16((dst) + (uint32_t)(rr * 260 + seg * 4) * 4,                   \
            (gptr) + (size_t)(bc * 32 + rr) * Dk + (ebase) + seg * 4);    \
    }                                                                     \
    cpa_commit();                                                         \
  }
#define CHUNK(accA, wbase, ehalf, buf)                                    \
  {                                                                       \
    const float4* pxc = (const float4*)(SM + (buf) + blw * 260);          \
    const ulonglong2* pw =                                                \
        (const ulonglong2*)(SM + (wbase)) + dp * 257 + (ehalf) * 128;     \
    _Pragma("unroll 8")                                                   \
    for (int e4 = 0; e4 < 64; e4++) {                                     \
      float4 q = pxc[e4];                                                 \
      ulonglong2 wA = pw[2 * e4], wB = pw[2 * e4 + 1];                    \
      ffma2(accA[0], dup2(q.x), wA.x);                                    \
      ffma2(accA[1], dup2(q.y), wA.y);                                    \
      ffma2(accA[2], dup2(q.z), wB.x);                                    \
      ffma2(accA[3], dup2(q.w), wB.y);                                    \
    }                                                                     \
  }

  for (int t = 0; t < Tk; t++) {
    const float* hin = &g_h[t & 1][0][0];
    // ============ Phase A: x = leaky(vec @ W_el + b_el) ============
    {
      if (tid < 32) {
        SM[OFF_SLT + tid] = __ldcg(&g_last_t[bc * 32 + tid]);
        ((int*)(SM + OFF_SLM))[tid] = __ldcg(&g_last_m[bc * 32 + tid]);
      }
      __syncthreads();
      // stage 32 emb rows into bufA (all threads, 4 each)
#pragma unroll
      for (int j = 0; j < 4; j++) {
        int id = tid + j * 512;
        int bl = id >> 6, seg = id & 63;
        cpa16(stA + (uint32_t)(bl * 260 + seg * 4) * 4,
              emb + (size_t)((int*)(SM + OFF_SLM))[bl] * Ek + seg * 4);
      }
      cpa_commit();
      if (half == 1) {
        // prefetch h chunks for phase B (h(t) is stable)
        STAGE_H(hin, 0, stB)
        STAGE_H(hin, 256, stC)
        cpa_wait_group<2>();   // emb done
      } else {
        cpa_wait_group<0>();   // emb done
      }
      __syncthreads();         // barrier AFTER waits -> emb copies all visible
      // vec fixup
      {
        int e = tid & 255;
        float wte = SM[OFF_WTE + e], bte = SM[OFF_BTE + e];
        float* sV = SM + OFF_BUFA;
#pragma unroll 4
        for (int bl = half * 16; bl < half * 16 + 16; bl++) {
          float te = __fadd_rn(__fmul_rn(SM[OFF_SLT + bl], wte), bte);
          sV[bl * 260 + e] = __fadd_rn(sV[bl * 260 + e], __fmul_rn(0.1f, te));
        }
      }
      __syncthreads();
      // dot: each half does its e-range
      {
        const float* pv = SM + OFF_BUFA + blw * 260 + half * 128;
        const unsigned long long* wa =
            (const unsigned long long*)(SM + OFF_WA) + half * 128 * 8;
        unsigned long long a0 = 0ull, a1 = 0ull;
#pragma unroll 8
        for (int e = 0; e < 128; e += 2) {
          ffma2(a0, dup2(pv[e]), wa[e * 8 + dp]);
          ffma2(a1, dup2(pv[e + 1]), wa[(e + 1) * 8 + dp]);
        }
        unsigned long long aH = add2(a0, a1);
        if (half == 1) sCMB[htid] = aH;
        __syncthreads();
        if (half == 0) {
          unsigned long long accT = add2(aH, sCMB[htid]);
          float v0, v1;
          asm("mov.b64 {%0, %1}, %2;" : "=f"(v0), "=f"(v1) : "l"(accT));
          v0 = __fadd_rn(v0, SM[OFF_BEL + d0]);
          v1 = __fadd_rn(v1, SM[OFF_BEL + d0 + 1]);
          float2 r;
          r.x = (v0 >= 0.0f) ? v0 : __fmul_rn(0.01f, v0);
          r.y = (v1 >= 0.0f) ? v1 : __fmul_rn(0.01f, v1);
          __stcg((float2*)&g_x[bg][d0], r);
        }
      }
      // neighbor meta + SE prefetch (overlaps phase B)
      int lm_my = ((int*)(SM + OFF_SLM))[dc];
      if (tid < Kk) {
        s_neigh[tid] = nlist[lm_my * Kk + tid];
        g_nrec[myb][1 + t * Kk + tid] = nprob[lm_my * Kk + tid];
      }
      __syncthreads();
#pragma unroll
      for (int j = 0; j < 2; j++) {
        int id = tid + j * 512;
        int k = id >> 6, seg = id & 63;
        cpa16(se_base + (uint32_t)(k * 256 + seg * 4) * 4,
              emb + (size_t)s_neigh[k] * Ek + seg * 4);
      }
      cpa_commit();
    }
    gbar(bc, epoch);

    // ==== Phase B: h' = tanh(x@Wih + b + h@Whh + b), split by operand ====
    {
      unsigned long long acc[4] = {0ull, 0ull, 0ull, 0ull};
      if (half == 0) {
        STAGE_H(&g_x[0][0], 0, stA)     // x0 -> A
        cpa_wait_group<0>();            // own copies done (incl. SE)
        hbar(1);                        // ALL half0 copies visible
        CHUNK(acc, OFF_WBI, 0, OFF_BUFA)
        hbar(1);                        // half0 done reading A
        STAGE_H(&g_x[0][0], 256, stA)   // x1 -> A
        cpa_wait_group<0>();
        hbar(1);                        // ALL half0 x1 copies visible
        CHUNK(acc, OFF_WBI, 1, OFF_BUFA)
      } else {
        cpa_wait_group<1>();            // own h0,h1 done (SE may pend)
        hbar(2);                        // ALL half1 h copies visible
        CHUNK(acc, OFF_WBH, 0, OFF_BUFB)
        CHUNK(acc, OFF_WBH, 1, OFF_BUFC)
        sCMB[htid] = add2(add2(acc[0], acc[1]), add2(acc[2], acc[3]));
      }
      __syncthreads();
      if (half == 0) {
        unsigned long long axT = add2(add2(acc[0], acc[1]), add2(acc[2], acc[3]));
        unsigned long long ahT = sCMB[htid];
        float ax0, ax1, ah0, ah1;
        asm("mov.b64 {%0, %1}, %2;" : "=f"(ax0), "=f"(ax1) : "l"(axT));
        asm("mov.b64 {%0, %1}, %2;" : "=f"(ah0), "=f"(ah1) : "l"(ahT));
        float2 r;
        r.x = tanhf(__fadd_rn(__fadd_rn(__fadd_rn(ax0, SM[OFF_BIH + d0]), ah0),
                              SM[OFF_BHH + d0]));
        r.y = tanhf(__fadd_rn(__fadd_rn(__fadd_rn(ax1, SM[OFF_BIH + d0 + 1]), ah1),
                              SM[OFF_BHH + d0 + 1]));
        __stcg((float2*)&g_h[(t + 1) & 1][bg][d0], r);
      }
    }
    gbar(bc, epoch);

    // ============ Phase C: sampling step for row myb ============
    {
      float* hb   = SM + OFF_BUFA;          // [512]
      float* red  = SM + OFF_CS;            // [16]
      float* redv = SM + OFF_CS + 16;       // [16]
      int*   ri   = (int*)(SM + OFF_CS + 32);
      float* sE   = SM + OFF_SE;

      cpa_wait_group<0>();                  // own SE copies done
      hb[tid] = __ldcg(&g_h[(t + 1) & 1][myb][tid]);
      __syncthreads();                      // all SE copies + hb visible

      // dt partial + warp reduce
      {
        float a = __fmul_rn(hb[tid], SM[OFF_WTM + tid]);
        for (int o = 16; o; o >>= 1)
          a = __fadd_rn(a, __shfl_down_sync(0xffffffffu, a, o));
        if (lane == 0) red[warp] = a;
      }

      // neighbor scores: warp k, 2-acc chains
      {
        const float* ev = sE + warp * 256;
        float acc0 = 0.0f, acc1 = 0.0f;
#pragma unroll
        for (int i = lane; i < Ek + Dk; i += 64) {
          float v0 = (i < Ek) ? ev[i] : hb[i - Ek];
          int i2 = i + 32;
          float v1 = (i2 < Ek) ? ev[i2] : hb[i2 - Ek];
          acc0 = fmaf(v0, SM[OFF_WMK + i], acc0);
          acc1 = fmaf(v1, SM[OFF_WMK + i2], acc1);
        }
        float acc = __fadd_rn(acc0, acc1);
        for (int o = 16; o; o >>= 1) acc += __shfl_down_sync(0xffffffffu, acc, o);
        if (lane == 0) s_score[warp] = __fadd_rn(acc, SM[OFF_BT + 1]);
      }
      __syncthreads();

      float newt = 0.0f;
      if (tid == 0) {
        float s = red[0];
        for (int w = 1; w < 16; w++) s = __fadd_rn(s, red[w]);
        float xx = __fadd_rn(s, SM[OFF_BT]);
        float sp = __fadd_rn(fmaxf(xx, 0.0f), log1pf(expf(-fabsf(xx))));
        newt = __fadd_rn(SM[OFF_BT + 2], sp);
      }

      // softmax + prob/cand update on warp 0 (lanes 0..15)
      if (warp == 0) {
        float sc = (lane < Kk) ? s_score[lane] : -3.4e38f;
        float mx = sc;
        for (int o = 8; o; o >>= 1)
          mx = fmaxf(mx, __shfl_xor_sync(0xffffffffu, mx, o));
        float ek = (lane < Kk) ? expf(__fadd_rn(sc, -mx)) : 0.0f;
        float ssum = 0.0f;
#pragma unroll
        for (int k = 0; k < Kk; k++)
          ssum = __fadd_rn(ssum, __shfl_sync(0xffffffffu, ek, k));
        float cp = sP[chosen];
        __syncwarp();
        if (lane < Kk) {
          float att = __fmul_rn(cp, __fdiv_rn(ek, ssum));
          if (lane == 0) {
            sP[chosen] = att;
          } else {
            int base = 1 + t * (Kk - 1);
            sP[base + lane - 1] = att;
            g_cand[myb][base + lane - 1] = s_neigh[lane];
          }
        }
      }
      __syncthreads();

      // gumbel-max over the active prefix (prob==0 beyond -> exactly -1e30)
      uint32_t k0, k1;
      tf2x32(0u, 42u, 0u, (uint32_t)t, k0, k1);
      int active = 15 * t + 16;
      if (active > Lk) active = Lk;
      float bv = -3.4e38f; int bi = 0x7fffffff;
      for (int l = tid; l < active; l += 512) {
        float pr = sP[l];
        float logit = (pr > 0.0f) ? logf(fmaxf(pr, 1e-38f)) : -1e30f;
        uint32_t i = (uint32_t)(myb * Lk + l);
        uint32_t o0, o1;
        tf2x32(k0, k1, 0u, i, o0, o1);
        uint32_t bits = o0 ^ o1;
        float u0 = __fadd_rn(__uint_as_float((bits >> 9) | 0x3f800000u), -1.0f);
        float u = fmaxf(TINYF, __fadd_rn(u0, TINYF));
        float gq = -logf(-logf(u));
        float v = __fadd_rn(logit, gq);
        if (v > bv) { bv = v; bi = l; }
      }
      for (int o = 16; o; o >>= 1) {
        float ov = __shfl_down_sync(0xffffffffu, bv, o);
        int   oi = __shfl_down_sync(0xffffffffu, bi, o);
        if (ov > bv || (ov == bv && oi < bi)) { bv = ov; bi = oi; }
      }
      if (lane == 0) { redv[warp] = bv; ri[warp] = bi; }
      __syncthreads();

      float bestv = redv[0]; int besti = ri[0];
      for (int w = 1; w < 16; w++) {
        if (redv[w] > bestv || (redv[w] == bestv && ri[w] < besti)) {
          bestv = redv[w]; besti = ri[w];
        }
      }
      chosen = besti;
      if (tid == 0) {
        int nm = g_cand[myb][besti];
        int col = t + 1;
        out[0 * 16384 + myb * Sk + col] = (float)nm;
        out[1 * 16384 + myb * Sk + col] = newt;
        out[2 * 16384 + myb * Sk + col] = (newt < 1000.0f) ? 1.0f : 0.0f;
        out[3 * 16384 + myb * Sk + col] = g_nrec[myb][besti];
        out[4 * 16384 + myb * Sk + col] = sP[besti];
        SM[OFF_BT + 2] = newt;
        __stcg(&g_last_m[myb], nm);
        __stcg(&g_last_t[myb], newt);
      }
    }
    gbar(bc, epoch);
  }
#undef STAGE_H
#undef CHUNK
}

extern "C" void kernel_launch(void* const* d_in, const int* in_sizes, int n_in,
                              void* d_out, int out_size) {
  const int*   marker = (const int*)d_in[0];
  const float* timed  = (const float*)d_in[1];
  const float* maskd  = (const float*)d_in[2];
  const float* emb    = (const float*)d_in[3];
  const int*   nlist  = (const int*)d_in[4];
  const float* nprob  = (const float*)d_in[5];
  const float* W_te   = (const float*)d_in[6];
  const float* b_te   = (const float*)d_in[7];
  const float* W_el   = (const float*)d_in[8];
  const float* b_el   = (const float*)d_in[9];
  const float* W_ih   = (const float*)d_in[10];
  const float* b_ih   = (const float*)d_in[11];
  const float* W_hh   = (const float*)d_in[12];
  const float* b_hh   = (const float*)d_in[13];
  const float* W_time = (const float*)d_in[14];
  const float* b_time = (const float*)d_in[15];
  const float* W_mk   = (const float*)d_in[16];
  const float* b_mk   = (const float*)d_in[17];
  float* out = (float*)d_out;

  cudaFuncSetAttribute(rnn_persistent,
                       cudaFuncAttributeMaxDynamicSharedMemorySize, SM_BYTES);
  reset_kernel<<<1, 128>>>();
  rnn_persistent<<<148, 512, SM_BYTES>>>(marker, timed, maskd, emb, nlist, nprob,
                                         W_te, b_te, W_el, b_el, W_ih, b_ih,
                                         W_hh, b_hh, W_time, b_time, W_mk, b_mk,
                                         out);
}

// round 13
// speedup vs baseline: 1.3707x; 1.2792x over previous
#include <cuda_runtime.h>
#include <cstdint>

#define Bk 128
#define Sk 128
#define Ek 256
#define Dk 512
#define Kk 16
#define Lk 1906
#define Rk 2033
#define Tk 127
#define TINYF 1.17549435e-38f

// smem layout (float offsets)
#define OFF_BUFA  0        // 32x260
#define OFF_BUFB  8320     // 32x260
#define OFF_BUFC  16640    // 32x260
#define OFF_WA    24960    // 256e x 8dp float2 = 4096
#define OFF_WBI   29056    // 8dp x 514 float2 = 8224
#define OFF_WBH   37280
#define OFF_SE    45504    // 16x256 = 4096
#define OFF_WMK   49600    // 768
#define OFF_WTM   50368    // 512
#define OFF_WTE   50880    // 256
#define OFF_BTE   51136    // 256
#define OFF_BEL   51392    // 512
#define OFF_BIH   51904    // 512
#define OFF_BHH   52416    // 512
#define OFF_BT    52928    // 4: b_time, b_mk, last_t_my
#define OFF_SLT   52932    // 32
#define OFF_SLM   52964    // 32
#define OFF_CS    52996    // red16 redv16 ri16 neigh16 score16 redp8 ripre8 = 96
#define OFF_CMB   53092    // 256 ULL = 512 floats (8B aligned: even)
#define OFF_SP    53604    // prob[1906]
#define SM_FLOATS 55510
#define SM_BYTES  (SM_FLOATS * 4)

__device__ float g_h[2][Bk][Dk];
__device__ float g_x[Bk][Dk];
__device__ float g_last_t[Bk];
__device__ int   g_last_m[Bk];
__device__ int   g_cand[Bk][Lk];
__device__ float g_nrec[Bk][Rk];
__device__ unsigned g_cnt[4][32];

// JAX threefry2x32 (exact)
__device__ __forceinline__ void tf2x32(uint32_t k0, uint32_t k1,
                                       uint32_t x0, uint32_t x1,
                                       uint32_t& o0, uint32_t& o1) {
  uint32_t ks2 = k0 ^ k1 ^ 0x1BD11BDAu;
  x0 += k0; x1 += k1;
#define RR(d) { x0 += x1; x1 = (x1 << d) | (x1 >> (32 - d)); x1 ^= x0; }
  RR(13) RR(15) RR(26) RR(6)  x0 += k1;  x1 += ks2 + 1u;
  RR(17) RR(29) RR(16) RR(24) x0 += ks2; x1 += k0 + 2u;
  RR(13) RR(15) RR(26) RR(6)  x0 += k0;  x1 += k1 + 3u;
  RR(17) RR(29) RR(16) RR(24) x0 += k1;  x1 += ks2 + 4u;
  RR(13) RR(15) RR(26) RR(6)  x0 += ks2; x1 += k0 + 5u;
#undef RR
  o0 = x0; o1 = x1;
}

// JAX uniform->gumbel bit recipe (exact)
__device__ __forceinline__ float gumbel_val(float pr, uint32_t k0, uint32_t k1,
                                            uint32_t i) {
  float logit = (pr > 0.0f) ? logf(fmaxf(pr, 1e-38f)) : -1e30f;
  uint32_t o0, o1;
  tf2x32(k0, k1, 0u, i, o0, o1);
  uint32_t bits = o0 ^ o1;
  float u0 = __fadd_rn(__uint_as_float((bits >> 9) | 0x3f800000u), -1.0f);
  float u = fmaxf(TINYF, __fadd_rn(u0, TINYF));
  float gq = -logf(-logf(u));
  return __fadd_rn(logit, gq);
}

__device__ __forceinline__ unsigned long long dup2(float v) {
  unsigned long long r;
  asm("mov.b64 %0, {%1, %1};" : "=l"(r) : "f"(v));
  return r;
}
__device__ __forceinline__ void ffma2(unsigned long long& acc,
                                      unsigned long long a,
                                      unsigned long long b) {
  asm("fma.rn.f32x2 %0, %1, %2, %3;" : "=l"(acc) : "l"(a), "l"(b), "l"(acc));
}
__device__ __forceinline__ unsigned long long add2(unsigned long long a,
                                                   unsigned long long b) {
  unsigned long long r;
  asm("add.rn.f32x2 %0, %1, %2;" : "=l"(r) : "l"(a), "l"(b));
  return r;
}
__device__ __forceinline__ void cpa16(uint32_t s, const void* g) {
  asm volatile("cp.async.cg.shared.global [%0], [%1], 16;"
               :: "r"(s), "l"(g) : "memory");
}
__device__ __forceinline__ void cpa_commit() {
  asm volatile("cp.async.commit_group;" ::: "memory");
}
template <int N>
__device__ __forceinline__ void cpa_wait_group() {
  asm volatile("cp.async.wait_group %0;" :: "n"(N) : "memory");
}
__device__ __forceinline__ void hbar(int id) {
  asm volatile("bar.sync %0, 256;" :: "r"(id) : "memory");
}

__global__ void reset_kernel() {
  if (threadIdx.x < 128) ((unsigned*)g_cnt)[threadIdx.x] = 0u;
}

// R8-proven barrier: release-red arrive + volatile poll on counter
__device__ __forceinline__ void gbar(int bc, unsigned& epoch) {
  __syncthreads();
  if (threadIdx.x == 0) {
    epoch += 32u;
    asm volatile("red.release.gpu.global.add.u32 [%0], %1;"
                 :: "l"(&g_cnt[bc][0]), "r"(1u) : "memory");
    while (*((volatile unsigned*)&g_cnt[bc][0]) < epoch) { }
  }
  __syncthreads();
}

__global__ void __launch_bounds__(512, 1)
rnn_persistent(const int* __restrict__ marker,
               const float* __restrict__ timed,
               const float* __restrict__ maskd,
               const float* __restrict__ emb,
               const int* __restrict__ nlist,
               const float* __restrict__ nprob,
               const float* __restrict__ W_te,
               const float* __restrict__ b_te,
               const float* __restrict__ W_el,
               const float* __restrict__ b_el,
               const float* __restrict__ W_ih,
               const float* __restrict__ b_ih,
               const float* __restrict__ W_hh,
               const float* __restrict__ b_hh,
               const float* __restrict__ W_time,
               const float* __restrict__ b_time,
               const float* __restrict__ W_mk,
               const float* __restrict__ b_mk,
               float* __restrict__ out) {
  extern __shared__ __align__(16) float SM[];
  const int BID = blockIdx.x;
  if (BID >= 128) return;
  const int tid = threadIdx.x;
  const int bc = BID >> 5;           // group (32 batch rows)
  const int dc = BID & 31;           // d tile (16 cols)
  const int myb = BID;
  unsigned epoch = 0;

  float* sP = SM + OFF_SP;

  // ---------------- one-time init ----------------
  for (int i = tid; i < Ek * 8; i += 512) {
    int e = i >> 3, dp8 = i & 7;
    ((float2*)(SM + OFF_WA))[e * 8 + dp8] =
        *(const float2*)&W_el[e * Dk + dc * 16 + dp8 * 2];
  }
  for (int i = tid; i < Dk * 8; i += 512) {
    int e = i >> 3, dp8 = i & 7;
    ((float2*)(SM + OFF_WBI))[dp8 * 514 + e] =
        *(const float2*)&W_ih[e * Dk + dc * 16 + dp8 * 2];
    ((float2*)(SM + OFF_WBH))[dp8 * 514 + e] =
        *(const float2*)&W_hh[e * Dk + dc * 16 + dp8 * 2];
  }
  for (int i = tid; i < Ek + Dk; i += 512) SM[OFF_WMK + i] = W_mk[i];
  if (tid < Dk) {
    SM[OFF_WTM + tid] = W_time[tid];
    SM[OFF_BEL + tid] = b_el[tid];
    SM[OFF_BIH + tid] = b_ih[tid];
    SM[OFF_BHH + tid] = b_hh[tid];
  }
  if (tid < Ek) { SM[OFF_WTE + tid] = W_te[tid]; SM[OFF_BTE + tid] = b_te[tid]; }
  if (tid == 0) {
    SM[OFF_BT] = b_time[0]; SM[OFF_BT + 1] = b_mk[0];
    SM[OFF_BT + 2] = timed[myb * Sk];
  }
  for (int l = tid; l < Lk; l += 512) {
    sP[l] = (l == 0) ? 1.0f : 0.0f;
    g_cand[myb][l] = (l == 0) ? marker[myb * Sk] : 0;
  }
  for (int r = tid; r < Rk; r += 512) g_nrec[myb][r] = 1.0f;
  for (int d = tid; d < Dk; d += 512) __stcg(&g_h[0][myb][d], 0.0f);
  int chosen = 0;
  if (tid == 0) {
    __stcg(&g_last_t[myb], timed[myb * Sk]);
    __stcg(&g_last_m[myb], marker[myb * Sk]);
    out[0 * 16384 + myb * Sk] = (float)marker[myb * Sk];
    out[1 * 16384 + myb * Sk] = timed[myb * Sk];
    out[2 * 16384 + myb * Sk] = maskd[myb * Sk];
    out[3 * 16384 + myb * Sk] = 1.0f;
    out[4 * 16384 + myb * Sk] = 1.0f;
  }
  gbar(bc, epoch);

  const int half = tid >> 8;          // 0: x-part, 1: h-part
  const int htid = tid & 255;
  const int dp = htid & 7;            // phase-A mapping (1 row per thread)
  const int blw = htid >> 3;
  const int d0 = dc * 16 + dp * 2;
  const int bg = bc * 32 + blw;
  // phase-B FMA mapping (2 rows per thread, htid<128)
  const int fdp = htid & 7;
  const int frg = (htid >> 3) & 15;
  const int d0f = dc * 16 + fdp * 2;
  const int warp = tid >> 5, lane = tid & 31;
  float* red  = SM + OFF_CS;            // [16]
  float* redv = SM + OFF_CS + 16;       // [16]
  int*   ri   = (int*)(SM + OFF_CS + 32);
  int*   s_neigh = (int*)(SM + OFF_CS + 48);
  float* s_score = SM + OFF_CS + 64;
  float* redp = SM + OFF_CS + 80;       // [8] prescan partial max
  int*   ripre = (int*)(SM + OFF_CS + 88);
  unsigned long long* sCMB = (unsigned long long*)(SM + OFF_CMB);
  const uint32_t stA = (uint32_t)__cvta_generic_to_shared(SM + OFF_BUFA);
  const uint32_t stB = (uint32_t)__cvta_generic_to_shared(SM + OFF_BUFB);
  const uint32_t stC = (uint32_t)__cvta_generic_to_shared(SM + OFF_BUFC);
  const uint32_t se_base = (uint32_t)__cvta_generic_to_shared(SM + OFF_SE);

#define STAGE_H(gptr, ebase, dst)                                         \
  {                                                                       \
    _Pragma("unroll")                                                     \
    for (int j = 0; j < 8; j++) {                                         \
      int id = htid + j * 256;                                            \
      int rr = id >> 6, seg = id & 63;                                    \
      cpa16((dst) + (uint32_t)(rr * 260 + seg * 4) * 4,                   \
            (gptr) + (size_t)(bc * 32 + rr) * Dk + (ebase) + seg * 4);    \
    }                                                                     \
    cpa_commit();                                                         \
  }
  // 2-row register-blocked chunk: rows frg, frg+16; weights read ONCE per pair
#define CHUNK2(wbase, ehalf, buf)                                         \
  {                                                                       \
    const float4* p0 = (const float4*)(SM + (buf) + frg * 260);           \
    const float4* p1 = (const float4*)(SM + (buf) + (frg + 16) * 260);    \
    const ulonglong2* pw =                                                \
        (const ulonglong2*)(SM + (wbase)) + fdp * 257 + (ehalf) * 128;    \
    _Pragma("unroll 8")                                                   \
    for (int e4 = 0; e4 < 64; e4++) {                                     \
      float4 q0 = p0[e4]; float4 q1 = p1[e4];                             \
      ulonglong2 wA = pw[2 * e4], wB = pw[2 * e4 + 1];                    \
      ffma2(a0, dup2(q0.x), wA.x); ffma2(b0, dup2(q1.x), wA.x);           \
      ffma2(a1, dup2(q0.y), wA.y); ffma2(b1, dup2(q1.y), wA.y);           \
      ffma2(a0, dup2(q0.z), wB.x); ffma2(b0, dup2(q1.z), wB.x);           \
      ffma2(a1, dup2(q0.w), wB.y); ffma2(b1, dup2(q1.w), wB.y);           \
    }                                                                     \
  }
  // prescan: argmax over untouched positions l in [0, base) \ {chosen}
#define PRESCAN()                                                         \
  {                                                                       \
    int ptid = (tid < 256) ? (tid - 128) : (tid - 256);                   \
    int base_p = 1 + t * (Kk - 1);                                        \
    uint32_t pk0, pk1;                                                    \
    tf2x32(0u, 42u, 0u, (uint32_t)t, pk0, pk1);                           \
    float bvp = -3.4e38f; int bip = 0x7fffffff;                           \
    for (int l = ptid; l < base_p; l += 256) {                            \
      if (l == chosen) continue;                                          \
      float v = gumbel_val(sP[l], pk0, pk1, (uint32_t)(myb * Lk + l));    \
      if (v > bvp) { bvp = v; bip = l; }                                  \
    }                                                                     \
    for (int o = 16; o; o >>= 1) {                                        \
      float ov = __shfl_down_sync(0xffffffffu, bvp, o);                   \
      int   oi = __shfl_down_sync(0xffffffffu, bip, o);                   \
      if (ov > bvp || (ov == bvp && oi < bip)) { bvp = ov; bip = oi; }    \
    }                                                                     \
    if (lane == 0) {                                                      \
      int slot = (warp < 8) ? (warp - 4) : (warp - 8);                    \
      redp[slot] = bvp; ripre[slot] = bip;                                \
    }                                                                     \
  }

  for (int t = 0; t < Tk; t++) {
    const float* hin = &g_h[t & 1][0][0];
    // ============ Phase A: x = leaky(vec @ W_el + b_el) ============
    {
      if (tid < 32) {
        SM[OFF_SLT + tid] = __ldcg(&g_last_t[bc * 32 + tid]);
        ((int*)(SM + OFF_SLM))[tid] = __ldcg(&g_last_m[bc * 32 + tid]);
      }
      __syncthreads();
#pragma unroll
      for (int j = 0; j < 4; j++) {
        int id = tid + j * 512;
        int bl = id >> 6, seg = id & 63;
        cpa16(stA + (uint32_t)(bl * 260 + seg * 4) * 4,
              emb + (size_t)((int*)(SM + OFF_SLM))[bl] * Ek + seg * 4);
      }
      cpa_commit();
      if (half == 1) {
        STAGE_H(hin, 0, stB)
        STAGE_H(hin, 256, stC)
        cpa_wait_group<2>();   // emb done
      } else {
        cpa_wait_group<0>();   // emb done
      }
      __syncthreads();
      {
        int e = tid & 255;
        float wte = SM[OFF_WTE + e], bte = SM[OFF_BTE + e];
        float* sV = SM + OFF_BUFA;
#pragma unroll 4
        for (int bl = half * 16; bl < half * 16 + 16; bl++) {
          float te = __fadd_rn(__fmul_rn(SM[OFF_SLT + bl], wte), bte);
          sV[bl * 260 + e] = __fadd_rn(sV[bl * 260 + e], __fmul_rn(0.1f, te));
        }
      }
      __syncthreads();
      // dot: each half its e-range (R12 scheme)
      {
        const float* pv = SM + OFF_BUFA + blw * 260 + half * 128;
        const unsigned long long* wa =
            (const unsigned long long*)(SM + OFF_WA) + half * 128 * 8;
        unsigned long long c0 = 0ull, c1 = 0ull;
#pragma unroll 8
        for (int e = 0; e < 128; e += 2) {
          ffma2(c0, dup2(pv[e]), wa[e * 8 + dp]);
          ffma2(c1, dup2(pv[e + 1]), wa[(e + 1) * 8 + dp]);
        }
        unsigned long long aH = add2(c0, c1);
        if (half == 1) sCMB[htid] = aH;
        __syncthreads();
        if (half == 0) {
          unsigned long long accT = add2(aH, sCMB[htid]);
          float v0, v1;
          asm("mov.b64 {%0, %1}, %2;" : "=f"(v0), "=f"(v1) : "l"(accT));
          v0 = __fadd_rn(v0, SM[OFF_BEL + d0]);
          v1 = __fadd_rn(v1, SM[OFF_BEL + d0 + 1]);
          float2 r;
          r.x = (v0 >= 0.0f) ? v0 : __fmul_rn(0.01f, v0);
          r.y = (v1 >= 0.0f) ? v1 : __fmul_rn(0.01f, v1);
          __stcg((float2*)&g_x[bg][d0], r);
        }
      }
      int lm_my = ((int*)(SM + OFF_SLM))[dc];
      if (tid < Kk) {
        s_neigh[tid] = nlist[lm_my * Kk + tid];
        g_nrec[myb][1 + t * Kk + tid] = nprob[lm_my * Kk + tid];
      }
      __syncthreads();
#pragma unroll
      for (int j = 0; j < 2; j++) {
        int id = tid + j * 512;
        int k = id >> 6, seg = id & 63;
        cpa16(se_base + (uint32_t)(k * 256 + seg * 4) * 4,
              emb + (size_t)s_neigh[k] * Ek + seg * 4);
      }
      cpa_commit();
    }
    gbar(bc, epoch);

    // ==== Phase B: h' = tanh(x@Wih+b + h@Whh+b); blocked FMA + prescan ====
    {
      unsigned long long a0 = 0ull, a1 = 0ull, b0 = 0ull, b1 = 0ull;
      if (half == 0) {
        STAGE_H(&g_x[0][0], 0, stA)     // x0 -> A (all 256)
        cpa_wait_group<0>();
        hbar(1);                        // x0 visible
        if (htid < 128) { CHUNK2(OFF_WBI, 0, OFF_BUFA) }
        else            { PRESCAN() }
        hbar(1);                        // x0 consumed + prescan half done
        STAGE_H(&g_x[0][0], 256, stA)   // x1 -> A
        cpa_wait_group<0>();
        hbar(1);                        // x1 visible
        if (htid < 128) { CHUNK2(OFF_WBI, 1, OFF_BUFA) }
      } else {
        cpa_wait_group<1>();            // h0,h1 done (SE may pend)
        hbar(2);                        // h visible to all half1
        if (htid < 128) {
          CHUNK2(OFF_WBH, 0, OFF_BUFB)
          CHUNK2(OFF_WBH, 1, OFF_BUFC)
          sCMB[frg * 8 + fdp]        = add2(a0, a1);
          sCMB[(frg + 16) * 8 + fdp] = add2(b0, b1);
        } else {
          PRESCAN()
        }
      }
      __syncthreads();
      if (tid < 128) {   // half0 FMA threads combine + write 2 rows
        unsigned long long axR0 = add2(a0, a1);
        unsigned long long axR1 = add2(b0, b1);
        unsigned long long ahR0 = sCMB[frg * 8 + fdp];
        unsigned long long ahR1 = sCMB[(frg + 16) * 8 + fdp];
        float x0v, x1v, h0v, h1v;
        float bi0 = SM[OFF_BIH + d0f], bi1 = SM[OFF_BIH + d0f + 1];
        float bh0 = SM[OFF_BHH + d0f], bh1 = SM[OFF_BHH + d0f + 1];
        asm("mov.b64 {%0, %1}, %2;" : "=f"(x0v), "=f"(x1v) : "l"(axR0));
        asm("mov.b64 {%0, %1}, %2;" : "=f"(h0v), "=f"(h1v) : "l"(ahR0));
        float2 r0;
        r0.x = tanhf(__fadd_rn(__fadd_rn(__fadd_rn(x0v, bi0), h0v), bh0));
        r0.y = tanhf(__fadd_rn(__fadd_rn(__fadd_rn(x1v, bi1), h1v), bh1));
        __stcg((float2*)&g_h[(t + 1) & 1][bc * 32 + frg][d0f], r0);
        asm("mov.b64 {%0, %1}, %2;" : "=f"(x0v), "=f"(x1v) : "l"(axR1));
        asm("mov.b64 {%0, %1}, %2;" : "=f"(h0v), "=f"(h1v) : "l"(ahR1));
        float2 r1;
        r1.x = tanhf(__fadd_rn(__fadd_rn(__fadd_rn(x0v, bi0), h0v), bh0));
        r1.y = tanhf(__fadd_rn(__fadd_rn(__fadd_rn(x1v, bi1), h1v), bh1));
        __stcg((float2*)&g_h[(t + 1) & 1][bc * 32 + frg + 16][d0f], r1);
      }
    }
    gbar(bc, epoch);

    // ============ Phase C: lightweight sampling (fresh-16 + merge) ========
    {
      float* hb = SM + OFF_BUFA;            // [512]
      float* sE = SM + OFF_SE;

      cpa_wait_group<0>();                  // SE landed
      hb[tid] = __ldcg(&g_h[(t + 1) & 1][myb][tid]);
      __syncthreads();

      // dt partial + warp reduce
      {
        float a = __fmul_rn(hb[tid], SM[OFF_WTM + tid]);
        for (int o = 16; o; o >>= 1)
          a = __fadd_rn(a, __shfl_down_sync(0xffffffffu, a, o));
        if (lane == 0) red[warp] = a;
      }

      // neighbor scores: warp k
      {
        const float* ev = sE + warp * 256;
        float acc0 = 0.0f, acc1 = 0.0f;
#pragma unroll
        for (int i = lane; i < Ek + Dk; i += 64) {
          float v0 = (i < Ek) ? ev[i] : hb[i - Ek];
          int i2 = i + 32;
          float v1 = (i2 < Ek) ? ev[i2] : hb[i2 - Ek];
          acc0 = fmaf(v0, SM[OFF_WMK + i], acc0);
          acc1 = fmaf(v1, SM[OFF_WMK + i2], acc1);
        }
        float acc = __fadd_rn(acc0, acc1);
        for (int o = 16; o; o >>= 1) acc += __shfl_down_sync(0xffffffffu, acc, o);
        if (lane == 0) s_score[warp] = __fadd_rn(acc, SM[OFF_BT + 1]);
      }
      __syncthreads();

      float newt = 0.0f;
      if (tid == 0) {
        float s = red[0];
        for (int w = 1; w < 16; w++) s = __fadd_rn(s, red[w]);
        float xx = __fadd_rn(s, SM[OFF_BT]);
        float sp = __fadd_rn(fmaxf(xx, 0.0f), log1pf(expf(-fabsf(xx))));
        newt = __fadd_rn(SM[OFF_BT + 2], sp);
      }

      // softmax + prob/cand updates + fresh-16 gumbel on warp 0
      if (warp == 0) {
        float sc = (lane < Kk) ? s_score[lane] : -3.4e38f;
        float mx = sc;
        for (int o = 8; o; o >>= 1)
          mx = fmaxf(mx, __shfl_xor_sync(0xffffffffu, mx, o));
        float ek = (lane < Kk) ? expf(__fadd_rn(sc, -mx)) : 0.0f;
        float ssum = 0.0f;
#pragma unroll
        for (int k = 0; k < Kk; k++)
          ssum = __fadd_rn(ssum, __shfl_sync(0xffffffffu, ek, k));
        float cp = sP[chosen];
        __syncwarp();
        float fv = -3.4e38f; int fi = 0x7fffffff;
        int base = 1 + t * (Kk - 1);
        if (lane < Kk) {
          float att = __fmul_rn(cp, __fdiv_rn(ek, ssum));
          int lf;
          if (lane == 0) {
            sP[chosen] = att;
            lf = chosen;
          } else {
            sP[base + lane - 1] = att;
            g_cand[myb][base + lane - 1] = s_neigh[lane];
            lf = base + lane - 1;
          }
          uint32_t ck0, ck1;
          tf2x32(0u, 42u, 0u, (uint32_t)t, ck0, ck1);
          fv = gumbel_val(att, ck0, ck1, (uint32_t)(myb * Lk + lf));
          fi = lf;
        }
        for (int o = 16; o; o >>= 1) {
          float ov = __shfl_down_sync(0xffffffffu, fv, o);
          int   oi = __shfl_down_sync(0xffffffffu, fi, o);
          if (ov > fv || (ov == fv && oi < fi)) { fv = ov; fi = oi; }
        }
        if (lane == 0) { redv[0] = fv; ri[0] = fi; }
      }
      __syncthreads();

      // merge fresh best with 8 prescan partials (all threads -> uniform)
      float bestv = redv[0]; int besti = ri[0];
#pragma unroll
      for (int s = 0; s < 8; s++) {
        float pv2 = redp[s]; int pi2 = ripre[s];
        if (pv2 > bestv || (pv2 == bestv && pi2 < besti)) {
          bestv = pv2; besti = pi2;
        }
      }
      chosen = besti;
      if (tid == 0) {
        int nm = g_cand[myb][besti];
        int col = t + 1;
        out[0 * 16384 + myb * Sk + col] = (float)nm;
        out[1 * 16384 + myb * Sk + col] = newt;
        out[2 * 16384 + myb * Sk + col] = (newt < 1000.0f) ? 1.0f : 0.0f;
        out[3 * 16384 + myb * Sk + col] = g_nrec[myb][besti];
        out[4 * 16384 + myb * Sk + col] = sP[besti];
        SM[OFF_BT + 2] = newt;
        __stcg(&g_last_m[myb], nm);
        __stcg(&g_last_t[myb], newt);
      }
    }
    gbar(bc, epoch);
  }
#undef STAGE_H
#undef CHUNK2
#undef PRESCAN
}

extern "C" void kernel_launch(void* const* d_in, const int* in_sizes, int n_in,
                              void* d_out, int out_size) {
  const int*   marker = (const int*)d_in[0];
  const float* timed  = (const float*)d_in[1];
  const float* maskd  = (const float*)d_in[2];
  const float* emb    = (const float*)d_in[3];
  const int*   nlist  = (const int*)d_in[4];
  const float* nprob  = (const float*)d_in[5];
  const float* W_te   = (const float*)d_in[6];
  const float* b_te   = (const float*)d_in[7];
  const float* W_el   = (const float*)d_in[8];
  const float* b_el   = (const float*)d_in[9];
  const float* W_ih   = (const float*)d_in[10];
  const float* b_ih   = (const float*)d_in[11];
  const float* W_hh   = (const float*)d_in[12];
  const float* b_hh   = (const float*)d_in[13];
  const float* W_time = (const float*)d_in[14];
  const float* b_time = (const float*)d_in[15];
  const float* W_mk   = (const float*)d_in[16];
  const float* b_mk   = (const float*)d_in[17];
  float* out = (float*)d_out;

  cudaFuncSetAttribute(rnn_persistent,
                       cudaFuncAttributeMaxDynamicSharedMemorySize, SM_BYTES);
  reset_kernel<<<1, 128>>>();
  rnn_persistent<<<148, 512, SM_BYTES>>>(marker, timed, maskd, emb, nlist, nprob,
                                         W_te, b_te, W_el, b_el, W_ih, b_ih,
                                         W_hh, b_hh, W_time, b_time, W_mk, b_mk,
                                         out);
}